// round 9
// baseline (speedup 1.0000x reference)
#include <cuda_runtime.h>
#include <cuda_bf16.h>
#include <cstdint>

#define NN 128

// ---- packed global operands (hi/lo bf16x2 planes) --------------------------
__device__ uint32_t g_SB[2048u * 16384u]; // S B-fmt [tile(b,t,e)]: hi h0 | hi h1 | lo h0 | lo h1 (4096 each)
__device__ uint32_t g_xA[1024u * 8192u];  // x A-fmt [tile(b,t)]: hi r*64+kp (4096), lo +4096
__device__ uint32_t g_xB[1024u * 8192u];  // x B64   [tile(b,t)]: hi n*32+kpf (4096), lo +4096
__device__ uint32_t g_HA[8u * 4096u];     // H chunks [e*4+k]: hi o*32+kpf (2048), lo +2048

// ---- smem word offsets -----------------------------------------------------
#define M1H  0
#define M1L  4352
#define M2H  8704
#define M2L  13056
#define SBW0 17408      // S half-buffers: half h: hi at 17408+h*9216, lo at 22016+h*9216
#define ZBH  35840
#define ZBL  40448
#define SMWORDS 45056   // 180224 bytes

// ---------------------------------------------------------------------------
__device__ __forceinline__ uint32_t pack_hi2(float a, float b) {
    uint32_t ua = (uint32_t)__bfloat16_as_ushort(__float2bfloat16(a));
    uint32_t ub = (uint32_t)__bfloat16_as_ushort(__float2bfloat16(b));
    return (ub << 16) | ua;
}
__device__ __forceinline__ uint32_t pack_lo2(float a, float b) {
    __nv_bfloat16 ha = __float2bfloat16(a);
    __nv_bfloat16 hb = __float2bfloat16(b);
    float ra = a - __bfloat162float(ha);
    float rb = b - __bfloat162float(hb);
    uint32_t ua = (uint32_t)__bfloat16_as_ushort(__float2bfloat16(ra));
    uint32_t ub = (uint32_t)__bfloat16_as_ushort(__float2bfloat16(rb));
    return (ub << 16) | ua;
}
__device__ __forceinline__ uint32_t smem_u32(const void* p) {
    uint32_t a;
    asm("{ .reg .u64 t; cvta.to.shared.u64 t, %1; cvt.u32.u64 %0, t; }" : "=r"(a) : "l"(p));
    return a;
}
__device__ __forceinline__ void ldsm4(uint32_t a, uint32_t& r0, uint32_t& r1,
                                      uint32_t& r2, uint32_t& r3) {
    asm volatile("ldmatrix.sync.aligned.m8n8.x4.shared.b16 {%0,%1,%2,%3}, [%4];"
                 : "=r"(r0), "=r"(r1), "=r"(r2), "=r"(r3) : "r"(a));
}

#define MMA_BF16(c, a0, a1, a2, a3, b0, b1)                                   \
    asm volatile(                                                             \
        "mma.sync.aligned.m16n8k16.row.col.f32.bf16.bf16.f32 "                \
        "{%0,%1,%2,%3}, {%4,%5,%6,%7}, {%8,%9}, {%0,%1,%2,%3};"               \
        : "+f"((c)[0]), "+f"((c)[1]), "+f"((c)[2]), "+f"((c)[3])              \
        : "r"(a0), "r"(a1), "r"(a2), "r"(a3), "r"(b0), "r"(b1))

// Round-robin 12-MMA block over 4 accumulators (reuse distance 4)
#define MMA_RR12(accA, accB, accC, accD,                                      \
                 h0,h1,h2,h3, l0,l1,l2,l3,                                    \
                 p0e,p0o,p1e,p1o, q0e,q0o,q1e,q1o,                            \
                 r0e,r0o,r1e,r1o, s0e,s0o,s1e,s1o)                            \
    do {                                                                      \
        MMA_BF16(accA, h0,h1,h2,h3, p0e,p1e);                                 \
        MMA_BF16(accB, h0,h1,h2,h3, p0o,p1o);                                 \
        MMA_BF16(accC, h0,h1,h2,h3, r0e,r1e);                                 \
        MMA_BF16(accD, h0,h1,h2,h3, r0o,r1o);                                 \
        MMA_BF16(accA, h0,h1,h2,h3, q0e,q1e);                                 \
        MMA_BF16(accB, h0,h1,h2,h3, q0o,q1o);                                 \
        MMA_BF16(accC, h0,h1,h2,h3, s0e,s1e);                                 \
        MMA_BF16(accD, h0,h1,h2,h3, s0o,s1o);                                 \
        MMA_BF16(accA, l0,l1,l2,l3, p0e,p1e);                                 \
        MMA_BF16(accB, l0,l1,l2,l3, p0o,p1o);                                 \
        MMA_BF16(accC, l0,l1,l2,l3, r0e,r1e);                                 \
        MMA_BF16(accD, l0,l1,l2,l3, r0o,r1o);                                 \
    } while (0)

// ---- async S-tile delivery -------------------------------------------------
__device__ __forceinline__ void prefetch_tile(uint32_t smb, const uint32_t* __restrict__ src,
                                              int tid) {
    #pragma unroll
    for (int h = 0; h < 2; h++) {
        uint32_t dh = smb + (uint32_t)((17408 + h * 9216) * 4);
        uint32_t dl = smb + (uint32_t)((22016 + h * 9216) * 4);
        const uint32_t* sh = src + h * 4096;
        const uint32_t* sl = src + 8192 + h * 4096;
        for (int w = tid; w < 1024; w += 256) {
            uint32_t off = (uint32_t)(((w >> 3) * 36 + (w & 7) * 4) * 4);
            asm volatile("cp.async.cg.shared.global [%0], [%1], 16;"
                         :: "r"(dh + off), "l"(sh + 4 * w));
            asm volatile("cp.async.cg.shared.global [%0], [%1], 16;"
                         :: "r"(dl + off), "l"(sl + 4 * w));
        }
    }
    asm volatile("cp.async.commit_group;");
}
#define CP_WAIT() asm volatile("cp.async.wait_group 0;" ::: "memory")

// ---- MMA cores -------------------------------------------------------------
__device__ __forceinline__ void mma_fullK_sA(uint32_t smb, int AHI, int ALO,
                                             float acc[8][4], int wm, int wn,
                                             int arow, int kcol)
{
    #pragma unroll
    for (int nt = 0; nt < 8; nt++)
        acc[nt][0] = acc[nt][1] = acc[nt][2] = acc[nt][3] = 0.f;
    uint32_t aH = smb + (uint32_t)((AHI + (16 * wm + arow) * 68 + kcol) * 4);
    uint32_t aL = smb + (uint32_t)((ALO + (16 * wm + arow) * 68 + kcol) * 4);
    #pragma unroll
    for (int h = 0; h < 2; h++) {
        uint32_t bH = smb + (uint32_t)((17408 + h * 9216 + (64 * wn + arow) * 36 + kcol) * 4);
        uint32_t bL = smb + (uint32_t)((22016 + h * 9216 + (64 * wn + arow) * 36 + kcol) * 4);
        #pragma unroll
        for (int kk = 0; kk < 4; kk++) {
            int k = 4 * h + kk;
            uint32_t ah0, ah1, ah2, ah3, al0, al1, al2, al3;
            ldsm4(aH + k * 32, ah0, ah1, ah2, ah3);
            ldsm4(aL + k * 32, al0, al1, al2, al3);
            #pragma unroll
            for (int gg = 0; gg < 4; gg += 2) {
                uint32_t p0e, p0o, p1e, p1o, q0e, q0o, q1e, q1o;
                uint32_t r0e, r0o, r1e, r1o, s0e, s0o, s1e, s1o;
                ldsm4(bH + gg * (16 * 36 * 4) + kk * 32, p0e, p0o, p1e, p1o);
                ldsm4(bL + gg * (16 * 36 * 4) + kk * 32, q0e, q0o, q1e, q1o);
                ldsm4(bH + (gg + 1) * (16 * 36 * 4) + kk * 32, r0e, r0o, r1e, r1o);
                ldsm4(bL + (gg + 1) * (16 * 36 * 4) + kk * 32, s0e, s0o, s1e, s1o);
                MMA_RR12(acc[2 * gg], acc[2 * gg + 1], acc[2 * gg + 2], acc[2 * gg + 3],
                         ah0, ah1, ah2, ah3, al0, al1, al2, al3,
                         p0e, p0o, p1e, p1o, q0e, q0o, q1e, q1o,
                         r0e, r0o, r1e, r1o, s0e, s0o, s1e, s1o);
            }
        }
    }
}
__device__ __forceinline__ void mma_fullK_gA(uint32_t smb, const uint32_t* __restrict__ gx,
                                             float acc[8][4], int wm, int wn,
                                             int arow, int kcol, int ra, int ca)
{
    #pragma unroll
    for (int nt = 0; nt < 8; nt++)
        acc[nt][0] = acc[nt][1] = acc[nt][2] = acc[nt][3] = 0.f;
    #pragma unroll
    for (int h = 0; h < 2; h++) {
        uint32_t bH = smb + (uint32_t)((17408 + h * 9216 + (64 * wn + arow) * 36 + kcol) * 4);
        uint32_t bL = smb + (uint32_t)((22016 + h * 9216 + (64 * wn + arow) * 36 + kcol) * 4);
        #pragma unroll
        for (int kk = 0; kk < 4; kk++) {
            int k = 4 * h + kk;
            int ab = (16 * wm + ra) * 64 + k * 8 + ca;
            uint32_t ah0 = gx[ab],        ah1 = gx[ab + 512];
            uint32_t ah2 = gx[ab + 4],    ah3 = gx[ab + 516];
            uint32_t al0 = gx[ab + 4096], al1 = gx[ab + 4608];
            uint32_t al2 = gx[ab + 4100], al3 = gx[ab + 4612];
            #pragma unroll
            for (int gg = 0; gg < 4; gg += 2) {
                uint32_t p0e, p0o, p1e, p1o, q0e, q0o, q1e, q1o;
                uint32_t r0e, r0o, r1e, r1o, s0e, s0o, s1e, s1o;
                ldsm4(bH + gg * (16 * 36 * 4) + kk * 32, p0e, p0o, p1e, p1o);
                ldsm4(bL + gg * (16 * 36 * 4) + kk * 32, q0e, q0o, q1e, q1o);
                ldsm4(bH + (gg + 1) * (16 * 36 * 4) + kk * 32, r0e, r0o, r1e, r1o);
                ldsm4(bL + (gg + 1) * (16 * 36 * 4) + kk * 32, s0e, s0o, s1e, s1o);
                MMA_RR12(acc[2 * gg], acc[2 * gg + 1], acc[2 * gg + 2], acc[2 * gg + 3],
                         ah0, ah1, ah2, ah3, al0, al1, al2, al3,
                         p0e, p0o, p1e, p1o, q0e, q0o, q1e, q1o,
                         r0e, r0o, r1e, r1o, s0e, s0o, s1e, s1o);
            }
        }
    }
}
__device__ __forceinline__ void mma_halfK_gH(uint32_t smb, const uint32_t* __restrict__ gh,
                                             float accY[8][4], int wm, int wn,
                                             int arow, int kcol, int ra, int ca)
{
    uint32_t bH = smb + (uint32_t)((ZBH + (64 * wn + arow) * 36 + kcol) * 4);
    uint32_t bL = smb + (uint32_t)((ZBL + (64 * wn + arow) * 36 + kcol) * 4);
    #pragma unroll
    for (int kk = 0; kk < 4; kk++) {
        int ab = (16 * wm + ra) * 32 + kk * 8 + ca;
        uint32_t ah0 = gh[ab],        ah1 = gh[ab + 256];
        uint32_t ah2 = gh[ab + 4],    ah3 = gh[ab + 260];
        uint32_t al0 = gh[ab + 2048], al1 = gh[ab + 2304];
        uint32_t al2 = gh[ab + 2052], al3 = gh[ab + 2308];
        #pragma unroll
        for (int gg = 0; gg < 4; gg += 2) {
            uint32_t p0e, p0o, p1e, p1o, q0e, q0o, q1e, q1o;
            uint32_t r0e, r0o, r1e, r1o, s0e, s0o, s1e, s1o;
            ldsm4(bH + gg * (16 * 36 * 4) + kk * 32, p0e, p0o, p1e, p1o);
            ldsm4(bL + gg * (16 * 36 * 4) + kk * 32, q0e, q0o, q1e, q1o);
            ldsm4(bH + (gg + 1) * (16 * 36 * 4) + kk * 32, r0e, r0o, r1e, r1o);
            ldsm4(bL + (gg + 1) * (16 * 36 * 4) + kk * 32, s0e, s0o, s1e, s1o);
            MMA_RR12(accY[2 * gg], accY[2 * gg + 1], accY[2 * gg + 2], accY[2 * gg + 3],
                     ah0, ah1, ah2, ah3, al0, al1, al2, al3,
                     p0e, p0o, p1e, p1o, q0e, q0o, q1e, q1o,
                     r0e, r0o, r1e, r1o, s0e, s0o, s1e, s1o);
        }
    }
}

// ---- acc -> smem staging ---------------------------------------------------
__device__ __forceinline__ void conv_A(uint32_t* sm, int AHI, int ALO,
                                       const float acc[8][4], int wm, int wn, int ra, int ca)
{
    int r0 = 16 * wm + ra;
    #pragma unroll
    for (int nt = 0; nt < 8; nt++) {
        int kp = 32 * wn + 4 * nt + ca;
        sm[AHI + r0 * 68 + kp]       = pack_hi2(acc[nt][0], acc[nt][1]);
        sm[ALO + r0 * 68 + kp]       = pack_lo2(acc[nt][0], acc[nt][1]);
        sm[AHI + (r0 + 8) * 68 + kp] = pack_hi2(acc[nt][2], acc[nt][3]);
        sm[ALO + (r0 + 8) * 68 + kp] = pack_lo2(acc[nt][2], acc[nt][3]);
    }
}
__device__ __forceinline__ void conv_ZB(uint32_t* sm, const float acc[8][4],
                                        int wm, int wn, int ra, int ca)
{
    #pragma unroll
    for (int nt = 0; nt < 8; nt++) {
        float o0 = __shfl_down_sync(0xffffffffu, acc[nt][0], 4);
        float o1 = __shfl_down_sync(0xffffffffu, acc[nt][1], 4);
        float o2 = __shfl_down_sync(0xffffffffu, acc[nt][2], 4);
        float o3 = __shfl_down_sync(0xffffffffu, acc[nt][3], 4);
        if (!(ra & 1)) {
            int c  = 64 * wn + nt * 8 + 2 * ca;
            int ka = 8 * wm + (ra >> 1);
            sm[ZBH + c * 36 + ka]           = pack_hi2(acc[nt][0], o0);
            sm[ZBL + c * 36 + ka]           = pack_lo2(acc[nt][0], o0);
            sm[ZBH + (c + 1) * 36 + ka]     = pack_hi2(acc[nt][1], o1);
            sm[ZBL + (c + 1) * 36 + ka]     = pack_lo2(acc[nt][1], o1);
            sm[ZBH + c * 36 + ka + 4]       = pack_hi2(acc[nt][2], o2);
            sm[ZBL + c * 36 + ka + 4]       = pack_lo2(acc[nt][2], o2);
            sm[ZBH + (c + 1) * 36 + ka + 4] = pack_hi2(acc[nt][3], o3);
            sm[ZBL + (c + 1) * 36 + ka + 4] = pack_lo2(acc[nt][3], o3);
        }
    }
}
__device__ __forceinline__ void copy_ZB(uint32_t* sm, const uint32_t* __restrict__ src, int tid) {
    const uint4* s4 = (const uint4*)src;
    for (int w = tid; w < 1024; w += 256) {
        int n = w >> 3, q = w & 7;
        *(uint4*)&sm[ZBH + n * 36 + 4 * q] = s4[w];
        *(uint4*)&sm[ZBL + n * 36 + 4 * q] = s4[1024 + w];
    }
}

// ===========================================================================
// Prep kernels
// ===========================================================================
__global__ void __launch_bounds__(256) conv_S_k(const float* __restrict__ S)
{
    extern __shared__ __align__(16) char smraw[];
    float* smT = (float*)smraw;                 // [128][130]
    int tile = blockIdx.x, tid = threadIdx.x;
    const float* Sp = S + (size_t)tile * 16384;
    for (int i = tid; i < 16384; i += 256) {
        int j = i >> 7, n = i & 127;
        smT[n * 130 + j] = Sp[i];
    }
    __syncthreads();
    uint32_t* dst = g_SB + (size_t)tile * 16384;
    for (int w = tid; w < 8192; w += 256) {
        int n = w >> 6, kp = w & 63;
        float2 v = *(const float2*)&smT[n * 130 + 2 * kp];
        int idx = (kp >> 5) * 4096 + n * 32 + (kp & 31);
        dst[idx]        = pack_hi2(v.x, v.y);
        dst[8192 + idx] = pack_lo2(v.x, v.y);
    }
}

__global__ void __launch_bounds__(256) conv_x_k(const float* __restrict__ x)
{
    __shared__ float smT[128 * 66];
    int tile = blockIdx.x, tid = threadIdx.x;
    const float* xp = x + (size_t)tile * 8192;
    uint32_t* da = g_xA + (size_t)tile * 8192;
    for (int w = tid; w < 4096; w += 256) {
        int r = w >> 6, kp = w & 63;
        float2 v = *(const float2*)(xp + r * NN + 2 * kp);
        da[w]        = pack_hi2(v.x, v.y);
        da[4096 + w] = pack_lo2(v.x, v.y);
    }
    for (int i = tid; i < 8192; i += 256) {
        int r = i >> 7, n = i & 127;
        smT[n * 66 + r] = xp[i];
    }
    __syncthreads();
    uint32_t* db = g_xB + (size_t)tile * 8192;
    for (int w = tid; w < 4096; w += 256) {
        int n = w >> 5, kpf = w & 31;
        float2 v = *(const float2*)&smT[n * 66 + 2 * kpf];
        db[w]        = pack_hi2(v.x, v.y);
        db[4096 + w] = pack_lo2(v.x, v.y);
    }
}

__global__ void __launch_bounds__(256) conv_H_k(const float* __restrict__ H)
{
    int tid = threadIdx.x;
    for (int w = tid; w < 8 * 2048; w += 256) {
        int c = w >> 11, o = (w >> 5) & 63, kpf = w & 31;
        int e = c >> 2, k = c & 3;
        int off = e * 256 + k * 64;
        float a  = H[o * 512 + off + 2 * kpf];
        float b2 = H[o * 512 + off + 2 * kpf + 1];
        g_HA[c * 4096 + o * 32 + kpf]        = pack_hi2(a, b2);
        g_HA[c * 4096 + 2048 + o * 32 + kpf] = pack_lo2(a, b2);
    }
}

__global__ void __launch_bounds__(256) y_init_k(const float* __restrict__ bias,
                                                float* __restrict__ y)
{
    int i = blockIdx.x * 256 + threadIdx.x;
    y[i] = bias[(i >> 7) & 63];
}

// ===========================================================================
// Persistent chain kernel: block = (b, e, 4-t chunk)
// ===========================================================================
__global__ void __launch_bounds__(256) chain_k(float* __restrict__ y)
{
    extern __shared__ __align__(16) uint32_t sm[];
    int bi = blockIdx.x;
    int ch = bi & 15, e = (bi >> 4) & 1, b = bi >> 5;
    int t0 = ch * 4;
    int tid = threadIdx.x;
    int wid = tid >> 5, lane = tid & 31;
    int wm = wid & 3, wn = wid >> 2;
    int ra = lane >> 2, ca = lane & 3;
    int g = lane >> 3, lr = lane & 7;
    int arow = (g & 1) * 8 + lr;
    int kcol = (g >> 1) * 4;

    uint32_t smb = smem_u32(sm);

    #define GSB(tt) (g_SB + (size_t)(((b * 64 + (tt)) * 2) + e) * 16384)
    #define GXA(tt) (g_xA + (size_t)(b * 64 + (tt)) * 8192)
    #define GXB(tt) (g_xB + (size_t)(b * 64 + (tt)) * 8192)

    float macc[8][4];

    // ---- warm-up: build M2 = tap2[t0-1], M1 = tap1[t0-1] ----
    if (ch > 0) {
        prefetch_tile(smb, GSB(t0 - 2), tid);
        CP_WAIT();
        __syncthreads();
        mma_fullK_gA(smb, GXA(t0 - 3), macc, wm, wn, arow, kcol, ra, ca);
        conv_A(sm, M2H, M2L, macc, wm, wn, ra, ca);
        __syncthreads();
        prefetch_tile(smb, GSB(t0 - 1), tid);
        CP_WAIT();
        __syncthreads();
        mma_fullK_sA(smb, M2H, M2L, macc, wm, wn, arow, kcol);
        __syncthreads();
        conv_A(sm, M2H, M2L, macc, wm, wn, ra, ca);
        mma_fullK_gA(smb, GXA(t0 - 2), macc, wm, wn, arow, kcol, ra, ca);
        conv_A(sm, M1H, M1L, macc, wm, wn, ra, ca);
        __syncthreads();
        prefetch_tile(smb, GSB(t0), tid);
    } else {
        prefetch_tile(smb, GSB(1), tid);
    }

    for (int t = t0; t < t0 + 4; t++) {
        float accY[8][4];
        #pragma unroll
        for (int nt = 0; nt < 8; nt++)
            accY[nt][0] = accY[nt][1] = accY[nt][2] = accY[nt][3] = 0.f;

        if (t == 0) {
            copy_ZB(sm, GXB(0), tid);
            __syncthreads();
            mma_halfK_gH(smb, g_HA + (size_t)(e * 4) * 4096, accY, wm, wn, arow, kcol, ra, ca);
            float* yp = y + (size_t)(b * 64) * 8192;
            int r0 = 16 * wm + ra;
            #pragma unroll
            for (int nt = 0; nt < 8; nt++) {
                int c = 64 * wn + nt * 8 + 2 * ca;
                atomicAdd(&yp[r0 * NN + c],           accY[nt][0]);
                atomicAdd(&yp[r0 * NN + c + 1],       accY[nt][1]);
                atomicAdd(&yp[(r0 + 8) * NN + c],     accY[nt][2]);
                atomicAdd(&yp[(r0 + 8) * NN + c + 1], accY[nt][3]);
            }
            continue;
        }

        CP_WAIT();            // S[t] halves resident
        __syncthreads();      // also: prev fold0 ZB readers done

        // ---- phase 3: m3 = M2 @ S, fold k=3 ----
        if (t >= 3) {
            mma_fullK_sA(smb, M2H, M2L, macc, wm, wn, arow, kcol);
            conv_ZB(sm, macc, wm, wn, ra, ca);
            __syncthreads();
            mma_halfK_gH(smb, g_HA + (size_t)(e * 4 + 3) * 4096, accY, wm, wn, arow, kcol, ra, ca);
        }
        // ---- phase 2: m2 = M1 @ S -> M2, fold k=2 ----
        if (t >= 2) {
            mma_fullK_sA(smb, M1H, M1L, macc, wm, wn, arow, kcol);
            conv_A(sm, M2H, M2L, macc, wm, wn, ra, ca);
            __syncthreads();
            conv_ZB(sm, macc, wm, wn, ra, ca);
            __syncthreads();
            mma_halfK_gH(smb, g_HA + (size_t)(e * 4 + 2) * 4096, accY, wm, wn, arow, kcol, ra, ca);
        }
        // ---- phase 1: m1 = x[t-1] @ S -> M1, fold k=1 ----
        {
            mma_fullK_gA(smb, GXA(t - 1), macc, wm, wn, arow, kcol, ra, ca);
            conv_A(sm, M1H, M1L, macc, wm, wn, ra, ca);
            __syncthreads();
            if (t < t0 + 3) prefetch_tile(smb, GSB(t + 1), tid);
            conv_ZB(sm, macc, wm, wn, ra, ca);
            __syncthreads();
            mma_halfK_gH(smb, g_HA + (size_t)(e * 4 + 1) * 4096, accY, wm, wn, arow, kcol, ra, ca);
        }
        // ---- phase 0: fold k=0 (tap0 = x[t]) ----
        __syncthreads();
        copy_ZB(sm, GXB(t), tid);
        __syncthreads();
        mma_halfK_gH(smb, g_HA + (size_t)(e * 4) * 4096, accY, wm, wn, arow, kcol, ra, ca);

        // ---- accumulate into y ----
        float* yp = y + (size_t)(b * 64 + t) * 8192;
        int r0 = 16 * wm + ra;
        #pragma unroll
        for (int nt = 0; nt < 8; nt++) {
            int c = 64 * wn + nt * 8 + 2 * ca;
            atomicAdd(&yp[r0 * NN + c],           accY[nt][0]);
            atomicAdd(&yp[r0 * NN + c + 1],       accY[nt][1]);
            atomicAdd(&yp[(r0 + 8) * NN + c],     accY[nt][2]);
            atomicAdd(&yp[(r0 + 8) * NN + c + 1], accY[nt][3]);
        }
    }
    #undef GSB
    #undef GXA
    #undef GXB
}

// ---------------------------------------------------------------------------
extern "C" void kernel_launch(void* const* d_in, const int* in_sizes, int n_in,
                              void* d_out, int out_size)
{
    const float* x    = (const float*)d_in[0];
    const float* S    = (const float*)d_in[1];
    const float* H    = (const float*)d_in[2];
    const float* bias = (const float*)d_in[3];
    float* y = (float*)d_out;

    cudaFuncSetAttribute(conv_S_k, cudaFuncAttributeMaxDynamicSharedMemorySize,
                         128 * 130 * 4);
    cudaFuncSetAttribute(chain_k, cudaFuncAttributeMaxDynamicSharedMemorySize,
                         SMWORDS * 4);

    conv_S_k<<<2048, 256, 128 * 130 * 4>>>(S);
    conv_x_k<<<1024, 256>>>(x);
    conv_H_k<<<1, 256>>>(H);
    y_init_k<<<32768, 256>>>(bias, y);

    chain_k<<<512, 256, SMWORDS * 4>>>(y);
}

// round 10
// speedup vs baseline: 1.1067x; 1.1067x over previous
#include <cuda_runtime.h>
#include <cuda_fp16.h>
#include <cstdint>

#define NN 128
#define TAPSZ (16*64*2*64*128)

__device__ float g_tap[3][TAPSZ];

// ---------------------------------------------------------------------------
__device__ __forceinline__ uint32_t pack_h2(float a, float b) {
    uint32_t ua = (uint32_t)__half_as_ushort(__float2half_rn(a));
    uint32_t ub = (uint32_t)__half_as_ushort(__float2half_rn(b));
    return (ub << 16) | ua;
}
__device__ __forceinline__ uint32_t pack_l2(float a, float b) {
    __half ha = __float2half_rn(a), hb = __float2half_rn(b);
    float ra = a - __half2float(ha), rb = b - __half2float(hb);
    uint32_t ua = (uint32_t)__half_as_ushort(__float2half_rn(ra));
    uint32_t ub = (uint32_t)__half_as_ushort(__float2half_rn(rb));
    return (ub << 16) | ua;
}
__device__ __forceinline__ uint32_t smem_u32(const void* p) {
    uint32_t a;
    asm("{ .reg .u64 t; cvta.to.shared.u64 t, %1; cvt.u32.u64 %0, t; }" : "=r"(a) : "l"(p));
    return a;
}
__device__ __forceinline__ void ldsm4(uint32_t a, uint32_t& r0, uint32_t& r1,
                                      uint32_t& r2, uint32_t& r3) {
    asm volatile("ldmatrix.sync.aligned.m8n8.x4.shared.b16 {%0,%1,%2,%3}, [%4];"
                 : "=r"(r0), "=r"(r1), "=r"(r2), "=r"(r3) : "r"(a));
}

#define MMA_F16(c, a0, a1, a2, a3, b0, b1)                                    \
    asm volatile(                                                             \
        "mma.sync.aligned.m16n8k16.row.col.f32.f16.f16.f32 "                  \
        "{%0,%1,%2,%3}, {%4,%5,%6,%7}, {%8,%9}, {%0,%1,%2,%3};"               \
        : "+f"((c)[0]), "+f"((c)[1]), "+f"((c)[2]), "+f"((c)[3])              \
        : "r"(a0), "r"(a1), "r"(a2), "r"(a3), "r"(b0), "r"(b1))

// ===========================================================================
// Diffusion: tap[pass][b,t,e] = in[b,t-1] @ S[b,t,e]   ([64,128] @ [128,128])
// A (in) = 2-plane fp16 [64 r][68 stride], B (S) = 1-plane fp16 [128 n][68]
// ===========================================================================
#define DA_H 0
#define DA_L 4352
#define DB   8704
#define D_WORDS 17408          // 69632 bytes -> 3 CTA/SM

__global__ void __launch_bounds__(256, 3) diffuse_k(
    const float* __restrict__ x, const float* __restrict__ S, int pass)
{
    extern __shared__ __align__(16) uint32_t sm[];
    int idx = blockIdx.x;
    int e = idx & 1, t = (idx >> 1) & 63, b = idx >> 7;
    int tid = threadIdx.x;

    float* out = &g_tap[pass][(size_t)((b * 64 + t) * 2 + e) * 8192];
    if (t == 0) {
        float4 z = make_float4(0.f, 0.f, 0.f, 0.f);
        for (int i = tid; i < 2048; i += 256) ((float4*)out)[i] = z;
        return;
    }
    const float* inp = (pass == 0)
        ? x + (size_t)(b * 64 + (t - 1)) * 8192
        : &g_tap[pass - 1][(size_t)((b * 64 + (t - 1)) * 2 + e) * 8192];
    const float* Sp = S + (size_t)((b * 64 + t) * 2 + e) * 16384;

    // A fill: 64 rows x 64 kp, hi/lo planes
    for (int i = tid; i < 4096; i += 256) {
        int r = i >> 6, kp = i & 63;
        float2 v = *(const float2*)(inp + r * NN + 2 * kp);
        sm[DA_H + r * 68 + kp] = pack_h2(v.x, v.y);
        sm[DA_L + r * 68 + kp] = pack_l2(v.x, v.y);
    }
    // B fill (transpose): 128 n x 64 kp, single plane
    for (int i = tid; i < 8192; i += 256) {
        int n = i & 127, kp = i >> 7;
        sm[DB + n * 68 + kp] = pack_h2(Sp[(2 * kp) * NN + n], Sp[(2 * kp + 1) * NN + n]);
    }
    __syncthreads();

    int wid = tid >> 5, lane = tid & 31;
    int wm = wid & 3, wn = wid >> 2;
    int ra = lane >> 2, ca = lane & 3;
    int g = lane >> 3, lr = lane & 7;
    int arow = (g & 1) * 8 + lr, kcol = (g >> 1) * 4;
    uint32_t smb = smem_u32(sm);
    uint32_t aH = smb + (uint32_t)((DA_H + (16 * wm + arow) * 68 + kcol) * 4);
    uint32_t aL = smb + (uint32_t)((DA_L + (16 * wm + arow) * 68 + kcol) * 4);
    uint32_t bB = smb + (uint32_t)((DB + (64 * wn + arow) * 68 + kcol) * 4);

    float acc[8][4];
    #pragma unroll
    for (int nt = 0; nt < 8; nt++)
        acc[nt][0] = acc[nt][1] = acc[nt][2] = acc[nt][3] = 0.f;

    #pragma unroll
    for (int k = 0; k < 8; k++) {
        uint32_t ah0, ah1, ah2, ah3, al0, al1, al2, al3;
        ldsm4(aH + k * 32, ah0, ah1, ah2, ah3);
        ldsm4(aL + k * 32, al0, al1, al2, al3);
        #pragma unroll
        for (int g2 = 0; g2 < 4; g2++) {
            uint32_t b0e, b0o, b1e, b1o;
            ldsm4(bB + g2 * (16 * 68 * 4) + k * 32, b0e, b0o, b1e, b1o);
            MMA_F16(acc[2 * g2],     ah0, ah1, ah2, ah3, b0e, b1e);
            MMA_F16(acc[2 * g2 + 1], ah0, ah1, ah2, ah3, b0o, b1o);
            MMA_F16(acc[2 * g2],     al0, al1, al2, al3, b0e, b1e);
            MMA_F16(acc[2 * g2 + 1], al0, al1, al2, al3, b0o, b1o);
        }
    }

    int r0 = 16 * wm + ra;
    #pragma unroll
    for (int nt = 0; nt < 8; nt++) {
        int c = 64 * wn + nt * 8 + 2 * ca;
        *(float2*)(out + r0 * NN + c)       = make_float2(acc[nt][0], acc[nt][1]);
        *(float2*)(out + (r0 + 8) * NN + c) = make_float2(acc[nt][2], acc[nt][3]);
    }
}

// ===========================================================================
// Projection: y[o][n] = bias[o] + sum_cc Hm[o][cc*64+f] * Z_cc[f][n]
// H chunk = 2-plane fp16 [64 o][36], Z chunk = 1-plane fp16 [128 n][36]
// ===========================================================================
#define PH_H 0
#define PH_L 2304
#define PZ   4608
#define P_WORDS 9216           // 36864 bytes

__global__ void __launch_bounds__(256, 3) proj_k(
    const float* __restrict__ x, const float* __restrict__ H,
    const float* __restrict__ bias, float* __restrict__ y)
{
    extern __shared__ __align__(16) uint32_t sm[];
    int t = blockIdx.x & 63, b = blockIdx.x >> 6;
    int tid = threadIdx.x;
    int wid = tid >> 5, lane = tid & 31;
    int wm = wid & 3, wn = wid >> 2;
    int ra = lane >> 2, ca = lane & 3;
    int g = lane >> 3, lr = lane & 7;
    int arow = (g & 1) * 8 + lr, kcol = (g >> 1) * 4;
    uint32_t smb = smem_u32(sm);

    float acc[8][4];
    #pragma unroll
    for (int nt = 0; nt < 8; nt++)
        acc[nt][0] = acc[nt][1] = acc[nt][2] = acc[nt][3] = 0.f;

    for (int cc = 0; cc < 8; cc++) {
        int e = cc >> 2, k = cc & 3;
        const float* zp = (k == 0)
            ? x + (size_t)(b * 64 + t) * 8192
            : &g_tap[k - 1][(size_t)((b * 64 + t) * 2 + e) * 8192];

        if (cc) __syncthreads();
        // H chunk: Hm[o][cc*64 + f], 2-plane
        for (int i = tid; i < 2048; i += 256) {
            int o = i >> 5, kp = i & 31;
            float2 v = *(const float2*)(H + o * 512 + cc * 64 + 2 * kp);
            sm[PH_H + o * 36 + kp] = pack_h2(v.x, v.y);
            sm[PH_L + o * 36 + kp] = pack_l2(v.x, v.y);
        }
        // Z chunk (transpose): 128 n x 32 kp, single plane
        for (int i = tid; i < 4096; i += 256) {
            int n = i & 127, kp = i >> 7;
            sm[PZ + n * 36 + kp] = pack_h2(zp[(2 * kp) * NN + n], zp[(2 * kp + 1) * NN + n]);
        }
        __syncthreads();

        uint32_t aH = smb + (uint32_t)((PH_H + (16 * wm + arow) * 36 + kcol) * 4);
        uint32_t aL = smb + (uint32_t)((PH_L + (16 * wm + arow) * 36 + kcol) * 4);
        uint32_t bB = smb + (uint32_t)((PZ + (64 * wn + arow) * 36 + kcol) * 4);
        #pragma unroll
        for (int kk = 0; kk < 4; kk++) {
            uint32_t ah0, ah1, ah2, ah3, al0, al1, al2, al3;
            ldsm4(aH + kk * 32, ah0, ah1, ah2, ah3);
            ldsm4(aL + kk * 32, al0, al1, al2, al3);
            #pragma unroll
            for (int g2 = 0; g2 < 4; g2++) {
                uint32_t b0e, b0o, b1e, b1o;
                ldsm4(bB + g2 * (16 * 36 * 4) + kk * 32, b0e, b0o, b1e, b1o);
                MMA_F16(acc[2 * g2],     ah0, ah1, ah2, ah3, b0e, b1e);
                MMA_F16(acc[2 * g2 + 1], ah0, ah1, ah2, ah3, b0o, b1o);
                MMA_F16(acc[2 * g2],     al0, al1, al2, al3, b0e, b1e);
                MMA_F16(acc[2 * g2 + 1], al0, al1, al2, al3, b0o, b1o);
            }
        }
    }

    float* yp = y + (size_t)(b * 64 + t) * 8192;
    int r0 = 16 * wm + ra;
    float bv0 = bias[r0], bv1 = bias[r0 + 8];
    #pragma unroll
    for (int nt = 0; nt < 8; nt++) {
        int c = 64 * wn + nt * 8 + 2 * ca;
        *(float2*)(yp + r0 * NN + c) =
            make_float2(acc[nt][0] + bv0, acc[nt][1] + bv0);
        *(float2*)(yp + (r0 + 8) * NN + c) =
            make_float2(acc[nt][2] + bv1, acc[nt][3] + bv1);
    }
}

// ---------------------------------------------------------------------------
extern "C" void kernel_launch(void* const* d_in, const int* in_sizes, int n_in,
                              void* d_out, int out_size)
{
    const float* x    = (const float*)d_in[0];
    const float* S    = (const float*)d_in[1];
    const float* H    = (const float*)d_in[2];
    const float* bias = (const float*)d_in[3];
    float* y = (float*)d_out;

    cudaFuncSetAttribute(diffuse_k, cudaFuncAttributeMaxDynamicSharedMemorySize,
                         D_WORDS * 4);

    for (int pass = 0; pass < 3; pass++)
        diffuse_k<<<16 * 64 * 2, 256, D_WORDS * 4>>>(x, S, pass);

    proj_k<<<16 * 64, 256, P_WORDS * 4>>>(x, H, bias, y);
}